// round 5
// baseline (speedup 1.0000x reference)
#include <cuda_runtime.h>
#include <cuda_fp16.h>
#include <cstdint>

// ---------------------------------------------------------------------------
// CLIPDecoder_83786222011049 — single-head MHA forward.
// Round 5: round-4 pipeline (f16 3-split mma.sync m16n8k16) with ldmatrix
// fragment loads (12 LDSM vs 48 LDS per k-step) + fused split launches.
// ---------------------------------------------------------------------------

static constexpr int L_DIM = 1024, NB = 16, E_DIMC = 1024;
static constexpr long long ME = (long long)L_DIM * NB;   // 16384

static constexpr int BM = 128, BN = 128, BK = 32, STAGES = 3;
static constexpr int TILE_B  = 128 * 80;           // 10240 B per matrix-half
static constexpr int AH_O = 0, AL_O = TILE_B, BH_O = 2 * TILE_B, BL_O = 3 * TILE_B;
static constexpr int STAGE_B = 4 * TILE_B;         // 40960
static constexpr int SMEM_REQ = STAGES * STAGE_B;  // 122880

// ---------------------------------------------------------------------------
// Scratch (device globals).
// ---------------------------------------------------------------------------
#define BIGH (size_t)(16384) * 1024
#define BATH (size_t)(16) * 1024 * 1024
__device__ __align__(256) __half g_xq_h[BIGH], g_xq_l[BIGH];
__device__ __align__(256) __half g_xk_h[BIGH], g_xk_l[BIGH];
__device__ __align__(256) __half g_xv_h[BIGH], g_xv_l[BIGH];
__device__ __align__(256) __half g_wq_h[1024*1024], g_wq_l[1024*1024];
__device__ __align__(256) __half g_wk_h[1024*1024], g_wk_l[1024*1024];
__device__ __align__(256) __half g_wv_h[1024*1024], g_wv_l[1024*1024];
__device__ __align__(256) __half g_q_h[BIGH], g_q_l[BIGH];
__device__ __align__(256) __half g_k_h[BIGH], g_k_l[BIGH];
__device__ __align__(256) float  g_v[BIGH];
__device__ __align__(256) __half g_vt_h[BATH], g_vt_l[BATH];
__device__ __align__(256) float  g_scores[BATH];
__device__ __align__(256) __half g_a_h[BATH], g_a_l[BATH];

// ---------------------------------------------------------------------------
// PTX helpers
// ---------------------------------------------------------------------------
__device__ __forceinline__ void cp16(uint32_t sdst, const void* gsrc) {
    asm volatile("cp.async.cg.shared.global [%0], [%1], 16;\n"
                 :: "r"(sdst), "l"(gsrc));
}
__device__ __forceinline__ void cp_commit() {
    asm volatile("cp.async.commit_group;\n" ::: "memory");
}
template <int N> __device__ __forceinline__ void cp_wait() {
    asm volatile("cp.async.wait_group %0;\n" :: "n"(N) : "memory");
}
__device__ __forceinline__ void ldsm4(uint32_t* r, uint32_t addr) {
    asm volatile("ldmatrix.sync.aligned.m8n8.x4.shared.b16 {%0,%1,%2,%3}, [%4];"
                 : "=r"(r[0]), "=r"(r[1]), "=r"(r[2]), "=r"(r[3]) : "r"(addr));
}
__device__ __forceinline__ void mma16(float* d, const uint32_t* a, const uint32_t* b) {
    asm volatile(
        "mma.sync.aligned.m16n8k16.row.col.f32.f16.f16.f32 "
        "{%0,%1,%2,%3},{%4,%5,%6,%7},{%8,%9},{%0,%1,%2,%3};\n"
        : "+f"(d[0]), "+f"(d[1]), "+f"(d[2]), "+f"(d[3])
        : "r"(a[0]), "r"(a[1]), "r"(a[2]), "r"(a[3]), "r"(b[0]), "r"(b[1]));
}
__device__ __forceinline__ uint32_t pk2h(float a, float b) {
    __half2 t = __floats2half2_rn(a, b);
    return *reinterpret_cast<uint32_t*>(&t);
}

extern __shared__ char dynsm[];

// ---------------------------------------------------------------------------
// GEMM (NT): D = Ah*Bh^T + Al*Bh^T + Ah*Bl^T.
// A: MxK k-major halves; B: NxK k-major halves. Batched via blockIdx.z.
// Epilogue: f = (acc*ascale + bias) * scale.
//   mode 0 -> Cf (fp32);  mode 1 -> Ch/Cl (f16 hi/lo split of f).
// ---------------------------------------------------------------------------
__global__ __launch_bounds__(256) void gemm_f16(
    const __half* __restrict__ Ah, const __half* __restrict__ Al,
    const __half* __restrict__ Bh, const __half* __restrict__ Bl,
    int K, long long lda, long long ldb, long long sA, long long sB,
    int mode, float* __restrict__ Cf,
    __half* __restrict__ Ch, __half* __restrict__ Cl,
    long long ldc, long long sC, const float* __restrict__ bias,
    float ascale, float scale)
{
    const uint32_t sbase = (uint32_t)__cvta_generic_to_shared(dynsm);
    const int tid = threadIdx.x, lane = tid & 31, warp = tid >> 5;
    const int wm = warp & 1, wn = warp >> 1;      // 2 x 4 warps
    const int q = lane & 3, g = lane >> 2;

    const long long m0 = (long long)blockIdx.y * BM;
    const long long n0 = (long long)blockIdx.x * BN;
    const long long bz = blockIdx.z;

    const char* Ahb = (const char*)(Ah + bz * sA + m0 * lda);
    const char* Alb = (const char*)(Al + bz * sA + m0 * lda);
    const char* Bhb = (const char*)(Bh + bz * sB + n0 * ldb);
    const char* Blb = (const char*)(Bl + bz * sB + n0 * ldb);

    // ldmatrix lane base offsets (bytes) within a stage's A / B tile.
    //   A x4: lanes 0-7 -> m 0-7 (k0-7) = a0; 8-15 -> m 8-15 = a1;
    //         16-23 -> m 0-7 (k8-15) = a2; 24-31 -> m 8-15 (k8-15) = a3.
    //   B x4: lanes 0-7 -> n 8j..8j+7 (k0-7); 8-15 same n (k8-15);
    //         16-31 -> next 8-n block  -> {b[2jp][0..1], b[2jp+1][0..1]}.
    const uint32_t aoff = (uint32_t)((wm * 64 + (lane & 15)) * 80 + ((lane >> 4) << 4));
    const uint32_t boff = (uint32_t)((wn * 32 + ((lane >> 4) & 1) * 8 + (lane & 7)) * 80
                                     + ((lane >> 3) & 1) * 16);

    float acc[4][4][4];
    #pragma unroll
    for (int i = 0; i < 4; ++i)
        #pragma unroll
        for (int j = 0; j < 4; ++j)
            #pragma unroll
            for (int r = 0; r < 4; ++r) acc[i][j][r] = 0.0f;

    const int KT = K / BK;
    const long long lda2 = lda * 2, ldb2 = ldb * 2;

    auto load_tile = [&](int kt) {
        const uint32_t sb = sbase + (kt % STAGES) * STAGE_B;
        const long long kb = (long long)kt * (BK * 2);   // byte offset in K
        const int row = tid >> 2, c = (tid & 3) * 16;
        #pragma unroll
        for (int p = 0; p < 2; ++p) {
            const int r = row + p * 64;
            const uint32_t d = (uint32_t)(r * 80 + c);
            const long long ga = (long long)r * lda2 + kb + c;
            const long long gb = (long long)r * ldb2 + kb + c;
            cp16(sb + AH_O + d, Ahb + ga);
            cp16(sb + AL_O + d, Alb + ga);
            cp16(sb + BH_O + d, Bhb + gb);
            cp16(sb + BL_O + d, Blb + gb);
        }
        cp_commit();
    };

    auto compute = [&](int kt) {
        const uint32_t sb = sbase + (kt % STAGES) * STAGE_B;
        #pragma unroll
        for (int kk = 0; kk < 2; ++kk) {
            const uint32_t ka = kk * 32;                  // byte offset of 16-k step
            uint32_t ah[4][4], al[4][4];
            #pragma unroll
            for (int i = 0; i < 4; ++i) {
                ldsm4(ah[i], sb + AH_O + aoff + i * 1280 + ka);
                ldsm4(al[i], sb + AL_O + aoff + i * 1280 + ka);
            }
            uint32_t bh[4][2], bl[4][2];
            #pragma unroll
            for (int jp = 0; jp < 2; ++jp) {
                uint32_t rb[4];
                ldsm4(rb, sb + BH_O + boff + jp * 1280 + ka);
                bh[2*jp][0] = rb[0]; bh[2*jp][1] = rb[1];
                bh[2*jp+1][0] = rb[2]; bh[2*jp+1][1] = rb[3];
                ldsm4(rb, sb + BL_O + boff + jp * 1280 + ka);
                bl[2*jp][0] = rb[0]; bl[2*jp][1] = rb[1];
                bl[2*jp+1][0] = rb[2]; bl[2*jp+1][1] = rb[3];
            }
            #pragma unroll
            for (int i = 0; i < 4; ++i)
                #pragma unroll
                for (int j = 0; j < 4; ++j) {
                    mma16(acc[i][j], ah[i], bh[j]);
                    mma16(acc[i][j], al[i], bh[j]);
                    mma16(acc[i][j], ah[i], bl[j]);
                }
        }
    };

    load_tile(0);
    load_tile(1);
    cp_wait<1>();
    __syncthreads();

    for (int kt = 0; kt < KT; ++kt) {
        if (kt + 2 < KT) load_tile(kt + 2);
        else             cp_commit();
        compute(kt);
        cp_wait<1>();
        __syncthreads();
    }

    // ---- epilogue ----
    #pragma unroll
    for (int i = 0; i < 4; ++i) {
        const long long r0 = m0 + wm * 64 + i * 16 + g;
        #pragma unroll
        for (int j = 0; j < 4; ++j) {
            const long long c0 = n0 + wn * 32 + j * 8 + 2 * q;
            const float b0 = bias ? bias[c0]     : 0.0f;
            const float b1 = bias ? bias[c0 + 1] : 0.0f;
            float x0 = (acc[i][j][0] * ascale + b0) * scale;
            float x1 = (acc[i][j][1] * ascale + b1) * scale;
            float x2 = (acc[i][j][2] * ascale + b0) * scale;
            float x3 = (acc[i][j][3] * ascale + b1) * scale;
            if (mode == 0) {
                *(float2*)(Cf + bz * sC + r0 * ldc + c0)       = make_float2(x0, x1);
                *(float2*)(Cf + bz * sC + (r0 + 8) * ldc + c0) = make_float2(x2, x3);
            } else {
                __half h0 = __float2half_rn(x0), h1 = __float2half_rn(x1);
                __half h2 = __float2half_rn(x2), h3 = __float2half_rn(x3);
                float l0 = x0 - __half2float(h0), l1 = x1 - __half2float(h1);
                float l2 = x2 - __half2float(h2), l3 = x3 - __half2float(h3);
                *(uint32_t*)(Ch + bz * sC + r0 * ldc + c0)       = pk2h(x0, x1);
                *(uint32_t*)(Ch + bz * sC + (r0 + 8) * ldc + c0) = pk2h(x2, x3);
                *(uint32_t*)(Cl + bz * sC + r0 * ldc + c0)       = pk2h(l0, l1);
                *(uint32_t*)(Cl + bz * sC + (r0 + 8) * ldc + c0) = pk2h(l2, l3);
            }
        }
    }
}

// ---------------------------------------------------------------------------
// fp32 -> (hi, lo) f16 split of x*scale; 3 arrays fused via blockIdx.y.
// ---------------------------------------------------------------------------
struct SplitArgs {
    const float* x[3];
    __half* h[3];
    __half* l[3];
};

__global__ __launch_bounds__(256) void split3_kernel(SplitArgs args, float scale)
{
    const int a = blockIdx.y;
    const long long i = (long long)blockIdx.x * 256 + threadIdx.x;
    float4 v = ((const float4*)args.x[a])[i];
    v.x *= scale; v.y *= scale; v.z *= scale; v.w *= scale;
    __half h0 = __float2half_rn(v.x), h1 = __float2half_rn(v.y);
    __half h2 = __float2half_rn(v.z), h3 = __float2half_rn(v.w);
    float l0 = v.x - __half2float(h0), l1 = v.y - __half2float(h1);
    float l2 = v.z - __half2float(h2), l3 = v.w - __half2float(h3);
    ((uint2*)args.h[a])[i] = make_uint2(pk2h(v.x, v.y), pk2h(v.z, v.w));
    ((uint2*)args.l[a])[i] = make_uint2(pk2h(l0, l1), pk2h(l2, l3));
}

// ---------------------------------------------------------------------------
// Transpose + split V:  v[(s*16+nb)*1024 + f] (fp32) -> vt{h,l}[nb][f][s]
// ---------------------------------------------------------------------------
__global__ __launch_bounds__(256) void transpose_split_kernel(
    const float* __restrict__ v, __half* __restrict__ vth,
    __half* __restrict__ vtl)
{
    __shared__ float t[64][65];
    const int nb = blockIdx.z;
    const int s0 = blockIdx.x * 64, f0 = blockIdx.y * 64;
    const int c = threadIdx.x & 63, r0 = threadIdx.x >> 6;

    #pragma unroll
    for (int rr = r0; rr < 64; rr += 4)
        t[rr][c] = v[(long long)((s0 + rr) * 16 + nb) * 1024 + f0 + c];
    __syncthreads();

    __half* oh = vth + (size_t)nb * 1024 * 1024;
    __half* ol = vtl + (size_t)nb * 1024 * 1024;
    #pragma unroll
    for (int rr = r0; rr < 64; rr += 4) {
        float x = t[c][rr];
        __half h = __float2half_rn(x);
        float lo = x - __half2float(h);
        size_t idx = (size_t)(f0 + rr) * 1024 + s0 + c;
        oh[idx] = h;
        ol[idx] = __float2half_rn(lo);
    }
}

// ---------------------------------------------------------------------------
// Row softmax over 1024 + f16 split of 256*p (keeps lo limbs normal-range).
// ---------------------------------------------------------------------------
__global__ __launch_bounds__(256) void softmax_split_kernel(
    const float* __restrict__ scores, __half* __restrict__ ah,
    __half* __restrict__ al)
{
    const long long row = blockIdx.x;
    const float* p = scores + row * 1024;
    const int t = threadIdx.x;

    float4 v = ((const float4*)p)[t];

    float m = fmaxf(fmaxf(v.x, v.y), fmaxf(v.z, v.w));
    #pragma unroll
    for (int o = 16; o > 0; o >>= 1)
        m = fmaxf(m, __shfl_xor_sync(0xFFFFFFFFu, m, o));
    __shared__ float smax[8], ssum[8];
    if ((t & 31) == 0) smax[t >> 5] = m;
    __syncthreads();
    float rowmax = smax[0];
    #pragma unroll
    for (int i = 1; i < 8; ++i) rowmax = fmaxf(rowmax, smax[i]);

    v.x = expf(v.x - rowmax); v.y = expf(v.y - rowmax);
    v.z = expf(v.z - rowmax); v.w = expf(v.w - rowmax);
    float s = v.x + v.y + v.z + v.w;
    #pragma unroll
    for (int o = 16; o > 0; o >>= 1)
        s += __shfl_xor_sync(0xFFFFFFFFu, s, o);
    if ((t & 31) == 0) ssum[t >> 5] = s;
    __syncthreads();
    float rowsum = 0.0f;
    #pragma unroll
    for (int i = 0; i < 8; ++i) rowsum += ssum[i];

    const float inv = 256.0f / rowsum;     // x256 keeps lo limbs normal-range
    v.x *= inv; v.y *= inv; v.z *= inv; v.w *= inv;

    __half h0 = __float2half_rn(v.x), h1 = __float2half_rn(v.y);
    __half h2 = __float2half_rn(v.z), h3 = __float2half_rn(v.w);
    float l0 = v.x - __half2float(h0), l1 = v.y - __half2float(h1);
    float l2 = v.z - __half2float(h2), l3 = v.w - __half2float(h3);
    ((uint2*)(ah + row * 1024))[t] = make_uint2(pk2h(v.x, v.y), pk2h(v.z, v.w));
    ((uint2*)(al + row * 1024))[t] = make_uint2(pk2h(l0, l1), pk2h(l2, l3));
}

// ---------------------------------------------------------------------------
// Launch
// ---------------------------------------------------------------------------
extern "C" void kernel_launch(void* const* d_in, const int* in_sizes, int n_in,
                              void* d_out, int out_size)
{
    const float* query = (const float*)d_in[0];
    const float* key   = (const float*)d_in[1];
    const float* value = (const float*)d_in[2];
    const float* wq    = (const float*)d_in[3];
    const float* wk    = (const float*)d_in[4];
    const float* wv    = (const float*)d_in[5];
    const float* bias  = (const float*)d_in[6];
    float* out = (float*)d_out;

    __half *xqh,*xql,*xkh,*xkl,*xvh,*xvl;
    __half *wqh,*wql,*wkh,*wkl,*wvh,*wvl;
    __half *qh,*ql,*kh,*kl,*vth,*vtl,*ath,*atl;
    float *vf, *sc;
    cudaGetSymbolAddress((void**)&xqh, g_xq_h); cudaGetSymbolAddress((void**)&xql, g_xq_l);
    cudaGetSymbolAddress((void**)&xkh, g_xk_h); cudaGetSymbolAddress((void**)&xkl, g_xk_l);
    cudaGetSymbolAddress((void**)&xvh, g_xv_h); cudaGetSymbolAddress((void**)&xvl, g_xv_l);
    cudaGetSymbolAddress((void**)&wqh, g_wq_h); cudaGetSymbolAddress((void**)&wql, g_wq_l);
    cudaGetSymbolAddress((void**)&wkh, g_wk_h); cudaGetSymbolAddress((void**)&wkl, g_wk_l);
    cudaGetSymbolAddress((void**)&wvh, g_wv_h); cudaGetSymbolAddress((void**)&wvl, g_wv_l);
    cudaGetSymbolAddress((void**)&qh,  g_q_h);  cudaGetSymbolAddress((void**)&ql,  g_q_l);
    cudaGetSymbolAddress((void**)&kh,  g_k_h);  cudaGetSymbolAddress((void**)&kl,  g_k_l);
    cudaGetSymbolAddress((void**)&vth, g_vt_h); cudaGetSymbolAddress((void**)&vtl, g_vt_l);
    cudaGetSymbolAddress((void**)&ath, g_a_h);  cudaGetSymbolAddress((void**)&atl, g_a_l);
    cudaGetSymbolAddress((void**)&vf,  g_v);
    cudaGetSymbolAddress((void**)&sc,  g_scores);

    cudaFuncSetAttribute(gemm_f16, cudaFuncAttributeMaxDynamicSharedMemorySize, SMEM_REQ);

    const long long MM = 1024LL * 1024;

    // 1) splits: inputs (scale 1), weights (scale 32 -> lo limbs stay normal)
    {
        SplitArgs in;
        in.x[0] = query; in.h[0] = xqh; in.l[0] = xql;
        in.x[1] = key;   in.h[1] = xkh; in.l[1] = xkl;
        in.x[2] = value; in.h[2] = xvh; in.l[2] = xvl;
        split3_kernel<<<dim3(16384, 3), 256>>>(in, 1.0f);
        SplitArgs w;
        w.x[0] = wq; w.h[0] = wqh; w.l[0] = wql;
        w.x[1] = wk; w.h[1] = wkh; w.l[1] = wkl;
        w.x[2] = wv; w.h[2] = wvh; w.l[2] = wvl;
        split3_kernel<<<dim3(1024, 3), 256>>>(w, 32.0f);
    }

    // 2) projections (M=16384, N=1024, K=1024); ascale=1/32 undoes weight x32.
    //    q written UNSCALED (E^-0.5 applied at the scores epilogue).
    {
        dim3 grid(1024 / BN, ME / BM, 1);
        gemm_f16<<<grid, 256, SMEM_REQ>>>(xqh, xql, wqh, wql, 1024, 1024, 1024, 0, 0,
                                          1, nullptr, qh, ql, 1024, 0,
                                          bias, 1.0f / 32.0f, 1.0f);
        gemm_f16<<<grid, 256, SMEM_REQ>>>(xkh, xkl, wkh, wkl, 1024, 1024, 1024, 0, 0,
                                          1, nullptr, kh, kl, 1024, 0,
                                          bias + 1024, 1.0f / 32.0f, 1.0f);
        gemm_f16<<<grid, 256, SMEM_REQ>>>(xvh, xvl, wvh, wvl, 1024, 1024, 1024, 0, 0,
                                          0, vf, nullptr, nullptr, 1024, 0,
                                          bias + 2048, 1.0f / 32.0f, 1.0f);
    }

    // 3) V transpose + split -> vt[nb][f][s]
    {
        dim3 grid(16, 16, 16);
        transpose_split_kernel<<<grid, 256>>>(vf, vth, vtl);
    }

    // 4) scores[nb] = (q[:,nb,:] @ k[:,nb,:]^T) * E^-0.5
    {
        dim3 grid(1024 / BN, 1024 / BM, 16);
        gemm_f16<<<grid, 256, SMEM_REQ>>>(qh, ql, kh, kl, 1024,
                                          16384, 16384, 1024, 1024,
                                          0, sc, nullptr, nullptr,
                                          1024, MM, nullptr, 1.0f, 1.0f / 32.0f);
    }

    // 5) softmax + split (outputs scaled x256)
    softmax_split_kernel<<<16 * 1024, 256>>>(sc, ath, atl);

    // 6) out[l][nb][f] = attn[nb] @ vt[nb]^T ; ascale=1/256 undoes attn x256
    {
        dim3 grid(1024 / BN, 1024 / BM, 16);
        gemm_f16<<<grid, 256, SMEM_REQ>>>(ath, atl, vth, vtl, 1024,
                                          1024, 1024, MM, MM,
                                          0, out, nullptr, nullptr,
                                          16384, 1024, nullptr, 1.0f / 256.0f, 1.0f);
    }
}

// round 6
// speedup vs baseline: 1.2105x; 1.2105x over previous
#include <cuda_runtime.h>
#include <cuda_fp16.h>
#include <cstdint>

// ---------------------------------------------------------------------------
// CLIPDecoder_83786222011049 — single-head MHA forward.
// Round 6: f16 3-split mma.sync m16n8k16 + ldmatrix, double-buffered
// (STAGES=2, 81920 B SMEM) so TWO CTAs fit per SM (16 warps) — cross-CTA
// latency hiding for the barrier/epilogue bubbles that capped tensor at 51%.
// ---------------------------------------------------------------------------

static constexpr int L_DIM = 1024, NB = 16, E_DIMC = 1024;
static constexpr long long ME = (long long)L_DIM * NB;   // 16384

static constexpr int BM = 128, BN = 128, BK = 32, STAGES = 2;
static constexpr int TILE_B  = 128 * 80;           // 10240 B per matrix-half
static constexpr int AH_O = 0, AL_O = TILE_B, BH_O = 2 * TILE_B, BL_O = 3 * TILE_B;
static constexpr int STAGE_B = 4 * TILE_B;         // 40960
static constexpr int SMEM_REQ = STAGES * STAGE_B;  // 81920 -> 2 CTAs/SM

// ---------------------------------------------------------------------------
// Scratch (device globals).
// ---------------------------------------------------------------------------
#define BIGH (size_t)(16384) * 1024
#define BATH (size_t)(16) * 1024 * 1024
__device__ __align__(256) __half g_xq_h[BIGH], g_xq_l[BIGH];
__device__ __align__(256) __half g_xk_h[BIGH], g_xk_l[BIGH];
__device__ __align__(256) __half g_xv_h[BIGH], g_xv_l[BIGH];
__device__ __align__(256) __half g_wq_h[1024*1024], g_wq_l[1024*1024];
__device__ __align__(256) __half g_wk_h[1024*1024], g_wk_l[1024*1024];
__device__ __align__(256) __half g_wv_h[1024*1024], g_wv_l[1024*1024];
__device__ __align__(256) __half g_q_h[BIGH], g_q_l[BIGH];
__device__ __align__(256) __half g_k_h[BIGH], g_k_l[BIGH];
__device__ __align__(256) float  g_v[BIGH];
__device__ __align__(256) __half g_vt_h[BATH], g_vt_l[BATH];
__device__ __align__(256) float  g_scores[BATH];
__device__ __align__(256) __half g_a_h[BATH], g_a_l[BATH];

// ---------------------------------------------------------------------------
// PTX helpers
// ---------------------------------------------------------------------------
__device__ __forceinline__ void cp16(uint32_t sdst, const void* gsrc) {
    asm volatile("cp.async.cg.shared.global [%0], [%1], 16;\n"
                 :: "r"(sdst), "l"(gsrc));
}
__device__ __forceinline__ void cp_commit() {
    asm volatile("cp.async.commit_group;\n" ::: "memory");
}
template <int N> __device__ __forceinline__ void cp_wait() {
    asm volatile("cp.async.wait_group %0;\n" :: "n"(N) : "memory");
}
__device__ __forceinline__ void ldsm4(uint32_t* r, uint32_t addr) {
    asm volatile("ldmatrix.sync.aligned.m8n8.x4.shared.b16 {%0,%1,%2,%3}, [%4];"
                 : "=r"(r[0]), "=r"(r[1]), "=r"(r[2]), "=r"(r[3]) : "r"(addr));
}
__device__ __forceinline__ void mma16(float* d, const uint32_t* a, const uint32_t* b) {
    asm volatile(
        "mma.sync.aligned.m16n8k16.row.col.f32.f16.f16.f32 "
        "{%0,%1,%2,%3},{%4,%5,%6,%7},{%8,%9},{%0,%1,%2,%3};\n"
        : "+f"(d[0]), "+f"(d[1]), "+f"(d[2]), "+f"(d[3])
        : "r"(a[0]), "r"(a[1]), "r"(a[2]), "r"(a[3]), "r"(b[0]), "r"(b[1]));
}
__device__ __forceinline__ uint32_t pk2h(float a, float b) {
    __half2 t = __floats2half2_rn(a, b);
    return *reinterpret_cast<uint32_t*>(&t);
}

extern __shared__ char dynsm[];

// ---------------------------------------------------------------------------
// GEMM (NT): D = Ah*Bh^T + Al*Bh^T + Ah*Bl^T.
// A: MxK k-major halves; B: NxK k-major halves. Batched via blockIdx.z.
// Epilogue: f = (acc*ascale + bias) * scale.
//   mode 0 -> Cf (fp32);  mode 1 -> Ch/Cl (f16 hi/lo split of f).
// ---------------------------------------------------------------------------
__global__ __launch_bounds__(256, 2) void gemm_f16(
    const __half* __restrict__ Ah, const __half* __restrict__ Al,
    const __half* __restrict__ Bh, const __half* __restrict__ Bl,
    int K, long long lda, long long ldb, long long sA, long long sB,
    int mode, float* __restrict__ Cf,
    __half* __restrict__ Ch, __half* __restrict__ Cl,
    long long ldc, long long sC, const float* __restrict__ bias,
    float ascale, float scale)
{
    const uint32_t sbase = (uint32_t)__cvta_generic_to_shared(dynsm);
    const int tid = threadIdx.x, lane = tid & 31, warp = tid >> 5;
    const int wm = warp & 1, wn = warp >> 1;      // 2 x 4 warps
    const int q = lane & 3, g = lane >> 2;

    const long long m0 = (long long)blockIdx.y * BM;
    const long long n0 = (long long)blockIdx.x * BN;
    const long long bz = blockIdx.z;

    const char* Ahb = (const char*)(Ah + bz * sA + m0 * lda);
    const char* Alb = (const char*)(Al + bz * sA + m0 * lda);
    const char* Bhb = (const char*)(Bh + bz * sB + n0 * ldb);
    const char* Blb = (const char*)(Bl + bz * sB + n0 * ldb);

    // ldmatrix lane base offsets (bytes) within a stage's A / B tiles.
    const uint32_t aoff = (uint32_t)((wm * 64 + (lane & 15)) * 80 + ((lane >> 4) << 4));
    const uint32_t boff = (uint32_t)((wn * 32 + ((lane >> 4) & 1) * 8 + (lane & 7)) * 80
                                     + ((lane >> 3) & 1) * 16);

    float acc[4][4][4];
    #pragma unroll
    for (int i = 0; i < 4; ++i)
        #pragma unroll
        for (int j = 0; j < 4; ++j)
            #pragma unroll
            for (int r = 0; r < 4; ++r) acc[i][j][r] = 0.0f;

    const int KT = K / BK;
    const long long lda2 = lda * 2, ldb2 = ldb * 2;

    auto load_tile = [&](int kt) {
        const uint32_t sb = sbase + (kt & 1) * STAGE_B;
        const long long kb = (long long)kt * (BK * 2);   // byte offset in K
        const int row = tid >> 2, c = (tid & 3) * 16;
        #pragma unroll
        for (int p = 0; p < 2; ++p) {
            const int r = row + p * 64;
            const uint32_t d = (uint32_t)(r * 80 + c);
            const long long ga = (long long)r * lda2 + kb + c;
            const long long gb = (long long)r * ldb2 + kb + c;
            cp16(sb + AH_O + d, Ahb + ga);
            cp16(sb + AL_O + d, Alb + ga);
            cp16(sb + BH_O + d, Bhb + gb);
            cp16(sb + BL_O + d, Blb + gb);
        }
        cp_commit();
    };

    auto compute = [&](int kt) {
        const uint32_t sb = sbase + (kt & 1) * STAGE_B;
        #pragma unroll
        for (int kk = 0; kk < 2; ++kk) {
            const uint32_t ka = kk * 32;                  // 16-k step, bytes
            uint32_t ah[4][4], al[4][4];
            #pragma unroll
            for (int i = 0; i < 4; ++i) {
                ldsm4(ah[i], sb + AH_O + aoff + i * 1280 + ka);
                ldsm4(al[i], sb + AL_O + aoff + i * 1280 + ka);
            }
            uint32_t bh[4][2], bl[4][2];
            #pragma unroll
            for (int jp = 0; jp < 2; ++jp) {
                uint32_t rb[4];
                ldsm4(rb, sb + BH_O + boff + jp * 1280 + ka);
                bh[2*jp][0] = rb[0]; bh[2*jp][1] = rb[1];
                bh[2*jp+1][0] = rb[2]; bh[2*jp+1][1] = rb[3];
                ldsm4(rb, sb + BL_O + boff + jp * 1280 + ka);
                bl[2*jp][0] = rb[0]; bl[2*jp][1] = rb[1];
                bl[2*jp+1][0] = rb[2]; bl[2*jp+1][1] = rb[3];
            }
            #pragma unroll
            for (int i = 0; i < 4; ++i)
                #pragma unroll
                for (int j = 0; j < 4; ++j) {
                    mma16(acc[i][j], ah[i], bh[j]);
                    mma16(acc[i][j], al[i], bh[j]);
                    mma16(acc[i][j], ah[i], bl[j]);
                }
        }
    };

    // Double-buffered mainloop (prefetch distance 1).
    load_tile(0);
    for (int kt = 0; kt < KT; ++kt) {
        if (kt + 1 < KT) load_tile(kt + 1);
        else             cp_commit();
        cp_wait<1>();          // stage kt resident
        __syncthreads();
        compute(kt);
        __syncthreads();       // guard stage reuse by load(kt+2) next iter
    }

    // ---- epilogue ----
    #pragma unroll
    for (int i = 0; i < 4; ++i) {
        const long long r0 = m0 + wm * 64 + i * 16 + g;
        #pragma unroll
        for (int j = 0; j < 4; ++j) {
            const long long c0 = n0 + wn * 32 + j * 8 + 2 * q;
            const float b0 = bias ? bias[c0]     : 0.0f;
            const float b1 = bias ? bias[c0 + 1] : 0.0f;
            float x0 = (acc[i][j][0] * ascale + b0) * scale;
            float x1 = (acc[i][j][1] * ascale + b1) * scale;
            float x2 = (acc[i][j][2] * ascale + b0) * scale;
            float x3 = (acc[i][j][3] * ascale + b1) * scale;
            if (mode == 0) {
                *(float2*)(Cf + bz * sC + r0 * ldc + c0)       = make_float2(x0, x1);
                *(float2*)(Cf + bz * sC + (r0 + 8) * ldc + c0) = make_float2(x2, x3);
            } else {
                __half h0 = __float2half_rn(x0), h1 = __float2half_rn(x1);
                __half h2 = __float2half_rn(x2), h3 = __float2half_rn(x3);
                float l0 = x0 - __half2float(h0), l1 = x1 - __half2float(h1);
                float l2 = x2 - __half2float(h2), l3 = x3 - __half2float(h3);
                *(uint32_t*)(Ch + bz * sC + r0 * ldc + c0)       = pk2h(x0, x1);
                *(uint32_t*)(Ch + bz * sC + (r0 + 8) * ldc + c0) = pk2h(x2, x3);
                *(uint32_t*)(Cl + bz * sC + r0 * ldc + c0)       = pk2h(l0, l1);
                *(uint32_t*)(Cl + bz * sC + (r0 + 8) * ldc + c0) = pk2h(l2, l3);
            }
        }
    }
}

// ---------------------------------------------------------------------------
// fp32 -> (hi, lo) f16 split of x*scale; 3 arrays fused via blockIdx.y.
// ---------------------------------------------------------------------------
struct SplitArgs {
    const float* x[3];
    __half* h[3];
    __half* l[3];
};

__global__ __launch_bounds__(256) void split3_kernel(SplitArgs args, float scale)
{
    const int a = blockIdx.y;
    const long long i = (long long)blockIdx.x * 256 + threadIdx.x;
    float4 v = ((const float4*)args.x[a])[i];
    v.x *= scale; v.y *= scale; v.z *= scale; v.w *= scale;
    __half h0 = __float2half_rn(v.x), h1 = __float2half_rn(v.y);
    __half h2 = __float2half_rn(v.z), h3 = __float2half_rn(v.w);
    float l0 = v.x - __half2float(h0), l1 = v.y - __half2float(h1);
    float l2 = v.z - __half2float(h2), l3 = v.w - __half2float(h3);
    ((uint2*)args.h[a])[i] = make_uint2(pk2h(v.x, v.y), pk2h(v.z, v.w));
    ((uint2*)args.l[a])[i] = make_uint2(pk2h(l0, l1), pk2h(l2, l3));
}

// ---------------------------------------------------------------------------
// Transpose + split V:  v[(s*16+nb)*1024 + f] (fp32) -> vt{h,l}[nb][f][s]
// ---------------------------------------------------------------------------
__global__ __launch_bounds__(256) void transpose_split_kernel(
    const float* __restrict__ v, __half* __restrict__ vth,
    __half* __restrict__ vtl)
{
    __shared__ float t[64][65];
    const int nb = blockIdx.z;
    const int s0 = blockIdx.x * 64, f0 = blockIdx.y * 64;
    const int c = threadIdx.x & 63, r0 = threadIdx.x >> 6;

    #pragma unroll
    for (int rr = r0; rr < 64; rr += 4)
        t[rr][c] = v[(long long)((s0 + rr) * 16 + nb) * 1024 + f0 + c];
    __syncthreads();

    __half* oh = vth + (size_t)nb * 1024 * 1024;
    __half* ol = vtl + (size_t)nb * 1024 * 1024;
    #pragma unroll
    for (int rr = r0; rr < 64; rr += 4) {
        float x = t[c][rr];
        __half h = __float2half_rn(x);
        float lo = x - __half2float(h);
        size_t idx = (size_t)(f0 + rr) * 1024 + s0 + c;
        oh[idx] = h;
        ol[idx] = __float2half_rn(lo);
    }
}

// ---------------------------------------------------------------------------
// Row softmax over 1024 + f16 split of 256*p (keeps lo limbs normal-range).
// ---------------------------------------------------------------------------
__global__ __launch_bounds__(256) void softmax_split_kernel(
    const float* __restrict__ scores, __half* __restrict__ ah,
    __half* __restrict__ al)
{
    const long long row = blockIdx.x;
    const float* p = scores + row * 1024;
    const int t = threadIdx.x;

    float4 v = ((const float4*)p)[t];

    float m = fmaxf(fmaxf(v.x, v.y), fmaxf(v.z, v.w));
    #pragma unroll
    for (int o = 16; o > 0; o >>= 1)
        m = fmaxf(m, __shfl_xor_sync(0xFFFFFFFFu, m, o));
    __shared__ float smax[8], ssum[8];
    if ((t & 31) == 0) smax[t >> 5] = m;
    __syncthreads();
    float rowmax = smax[0];
    #pragma unroll
    for (int i = 1; i < 8; ++i) rowmax = fmaxf(rowmax, smax[i]);

    v.x = expf(v.x - rowmax); v.y = expf(v.y - rowmax);
    v.z = expf(v.z - rowmax); v.w = expf(v.w - rowmax);
    float s = v.x + v.y + v.z + v.w;
    #pragma unroll
    for (int o = 16; o > 0; o >>= 1)
        s += __shfl_xor_sync(0xFFFFFFFFu, s, o);
    if ((t & 31) == 0) ssum[t >> 5] = s;
    __syncthreads();
    float rowsum = 0.0f;
    #pragma unroll
    for (int i = 0; i < 8; ++i) rowsum += ssum[i];

    const float inv = 256.0f / rowsum;     // x256 keeps lo limbs normal-range
    v.x *= inv; v.y *= inv; v.z *= inv; v.w *= inv;

    __half h0 = __float2half_rn(v.x), h1 = __float2half_rn(v.y);
    __half h2 = __float2half_rn(v.z), h3 = __float2half_rn(v.w);
    float l0 = v.x - __half2float(h0), l1 = v.y - __half2float(h1);
    float l2 = v.z - __half2float(h2), l3 = v.w - __half2float(h3);
    ((uint2*)(ah + row * 1024))[t] = make_uint2(pk2h(v.x, v.y), pk2h(v.z, v.w));
    ((uint2*)(al + row * 1024))[t] = make_uint2(pk2h(l0, l1), pk2h(l2, l3));
}

// ---------------------------------------------------------------------------
// Launch
// ---------------------------------------------------------------------------
extern "C" void kernel_launch(void* const* d_in, const int* in_sizes, int n_in,
                              void* d_out, int out_size)
{
    const float* query = (const float*)d_in[0];
    const float* key   = (const float*)d_in[1];
    const float* value = (const float*)d_in[2];
    const float* wq    = (const float*)d_in[3];
    const float* wk    = (const float*)d_in[4];
    const float* wv    = (const float*)d_in[5];
    const float* bias  = (const float*)d_in[6];
    float* out = (float*)d_out;

    __half *xqh,*xql,*xkh,*xkl,*xvh,*xvl;
    __half *wqh,*wql,*wkh,*wkl,*wvh,*wvl;
    __half *qh,*ql,*kh,*kl,*vth,*vtl,*ath,*atl;
    float *vf, *sc;
    cudaGetSymbolAddress((void**)&xqh, g_xq_h); cudaGetSymbolAddress((void**)&xql, g_xq_l);
    cudaGetSymbolAddress((void**)&xkh, g_xk_h); cudaGetSymbolAddress((void**)&xkl, g_xk_l);
    cudaGetSymbolAddress((void**)&xvh, g_xv_h); cudaGetSymbolAddress((void**)&xvl, g_xv_l);
    cudaGetSymbolAddress((void**)&wqh, g_wq_h); cudaGetSymbolAddress((void**)&wql, g_wq_l);
    cudaGetSymbolAddress((void**)&wkh, g_wk_h); cudaGetSymbolAddress((void**)&wkl, g_wk_l);
    cudaGetSymbolAddress((void**)&wvh, g_wv_h); cudaGetSymbolAddress((void**)&wvl, g_wv_l);
    cudaGetSymbolAddress((void**)&qh,  g_q_h);  cudaGetSymbolAddress((void**)&ql,  g_q_l);
    cudaGetSymbolAddress((void**)&kh,  g_k_h);  cudaGetSymbolAddress((void**)&kl,  g_k_l);
    cudaGetSymbolAddress((void**)&vth, g_vt_h); cudaGetSymbolAddress((void**)&vtl, g_vt_l);
    cudaGetSymbolAddress((void**)&ath, g_a_h);  cudaGetSymbolAddress((void**)&atl, g_a_l);
    cudaGetSymbolAddress((void**)&vf,  g_v);
    cudaGetSymbolAddress((void**)&sc,  g_scores);

    cudaFuncSetAttribute(gemm_f16, cudaFuncAttributeMaxDynamicSharedMemorySize, SMEM_REQ);

    const long long MM = 1024LL * 1024;

    // 1) splits: inputs (scale 1), weights (scale 32 -> lo limbs stay normal)
    {
        SplitArgs in;
        in.x[0] = query; in.h[0] = xqh; in.l[0] = xql;
        in.x[1] = key;   in.h[1] = xkh; in.l[1] = xkl;
        in.x[2] = value; in.h[2] = xvh; in.l[2] = xvl;
        split3_kernel<<<dim3(16384, 3), 256>>>(in, 1.0f);
        SplitArgs w;
        w.x[0] = wq; w.h[0] = wqh; w.l[0] = wql;
        w.x[1] = wk; w.h[1] = wkh; w.l[1] = wkl;
        w.x[2] = wv; w.h[2] = wvh; w.l[2] = wvl;
        split3_kernel<<<dim3(1024, 3), 256>>>(w, 32.0f);
    }

    // 2) projections (M=16384, N=1024, K=1024); ascale=1/32 undoes weight x32.
    {
        dim3 grid(1024 / BN, ME / BM, 1);
        gemm_f16<<<grid, 256, SMEM_REQ>>>(xqh, xql, wqh, wql, 1024, 1024, 1024, 0, 0,
                                          1, nullptr, qh, ql, 1024, 0,
                                          bias, 1.0f / 32.0f, 1.0f);
        gemm_f16<<<grid, 256, SMEM_REQ>>>(xkh, xkl, wkh, wkl, 1024, 1024, 1024, 0, 0,
                                          1, nullptr, kh, kl, 1024, 0,
                                          bias + 1024, 1.0f / 32.0f, 1.0f);
        gemm_f16<<<grid, 256, SMEM_REQ>>>(xvh, xvl, wvh, wvl, 1024, 1024, 1024, 0, 0,
                                          0, vf, nullptr, nullptr, 1024, 0,
                                          bias + 2048, 1.0f / 32.0f, 1.0f);
    }

    // 3) V transpose + split -> vt[nb][f][s]
    {
        dim3 grid(16, 16, 16);
        transpose_split_kernel<<<grid, 256>>>(vf, vth, vtl);
    }

    // 4) scores[nb] = (q[:,nb,:] @ k[:,nb,:]^T) * E^-0.5
    {
        dim3 grid(1024 / BN, 1024 / BM, 16);
        gemm_f16<<<grid, 256, SMEM_REQ>>>(qh, ql, kh, kl, 1024,
                                          16384, 16384, 1024, 1024,
                                          0, sc, nullptr, nullptr,
                                          1024, MM, nullptr, 1.0f, 1.0f / 32.0f);
    }

    // 5) softmax + split (outputs scaled x256)
    softmax_split_kernel<<<16 * 1024, 256>>>(sc, ath, atl);

    // 6) out[l][nb][f] = attn[nb] @ vt[nb]^T ; ascale=1/256 undoes attn x256
    {
        dim3 grid(1024 / BN, 1024 / BM, 16);
        gemm_f16<<<grid, 256, SMEM_REQ>>>(ath, atl, vth, vtl, 1024,
                                          1024, 1024, MM, MM,
                                          0, out, nullptr, nullptr,
                                          16384, 1024, nullptr, 1.0f / 256.0f, 1.0f);
    }
}

// round 7
// speedup vs baseline: 1.2319x; 1.0177x over previous
#include <cuda_runtime.h>
#include <cuda_fp16.h>
#include <cstdint>

// ---------------------------------------------------------------------------
// CLIPDecoder_83786222011049 — single-head MHA forward.
// Round 7: f16 3-split mma.sync + ldmatrix, 2 CTAs/SM; merged projection
// launch; softmax fused into scores-GEMM epilogue (exp + deterministic
// row-sum partials) with AV-epilogue normalization; 1 barrier per K-iter.
// ---------------------------------------------------------------------------

static constexpr int BM = 128, BN = 128, BK = 32;
static constexpr int TILE_B  = 128 * 80;           // 10240 B per matrix-half
static constexpr int AH_O = 0, AL_O = TILE_B, BH_O = 2 * TILE_B, BL_O = 3 * TILE_B;
static constexpr int STAGE_B = 4 * TILE_B;         // 40960
static constexpr int SMEM_REQ = 2 * STAGE_B;       // 81920 -> 2 CTAs/SM

// ---------------------------------------------------------------------------
// Scratch (device globals).
// ---------------------------------------------------------------------------
#define BIGH (size_t)(16384) * 1024
#define BATH (size_t)(16) * 1024 * 1024
__device__ __align__(256) __half g_xq_h[BIGH], g_xq_l[BIGH];
__device__ __align__(256) __half g_xk_h[BIGH], g_xk_l[BIGH];
__device__ __align__(256) __half g_xv_h[BIGH], g_xv_l[BIGH];
__device__ __align__(256) __half g_wq_h[1024*1024], g_wq_l[1024*1024];
__device__ __align__(256) __half g_wk_h[1024*1024], g_wk_l[1024*1024];
__device__ __align__(256) __half g_wv_h[1024*1024], g_wv_l[1024*1024];
__device__ __align__(256) __half g_q_h[BIGH], g_q_l[BIGH];
__device__ __align__(256) __half g_k_h[BIGH], g_k_l[BIGH];
__device__ __align__(256) float  g_v[BIGH];
__device__ __align__(256) __half g_vt_h[BATH], g_vt_l[BATH];
__device__ __align__(256) __half g_a_h[BATH], g_a_l[BATH];
__device__ __align__(256) float  g_part[(size_t)16 * 1024 * 8];
__device__ __align__(256) float  g_rsum[(size_t)16 * 1024];

// ---------------------------------------------------------------------------
// PTX helpers
// ---------------------------------------------------------------------------
__device__ __forceinline__ void cp16(uint32_t sdst, const void* gsrc) {
    asm volatile("cp.async.cg.shared.global [%0], [%1], 16;\n"
                 :: "r"(sdst), "l"(gsrc));
}
__device__ __forceinline__ void cp_commit() {
    asm volatile("cp.async.commit_group;\n" ::: "memory");
}
template <int N> __device__ __forceinline__ void cp_wait() {
    asm volatile("cp.async.wait_group %0;\n" :: "n"(N) : "memory");
}
__device__ __forceinline__ void ldsm4(uint32_t* r, uint32_t addr) {
    asm volatile("ldmatrix.sync.aligned.m8n8.x4.shared.b16 {%0,%1,%2,%3}, [%4];"
                 : "=r"(r[0]), "=r"(r[1]), "=r"(r[2]), "=r"(r[3]) : "r"(addr));
}
__device__ __forceinline__ void mma16(float* d, const uint32_t* a, const uint32_t* b) {
    asm volatile(
        "mma.sync.aligned.m16n8k16.row.col.f32.f16.f16.f32 "
        "{%0,%1,%2,%3},{%4,%5,%6,%7},{%8,%9},{%0,%1,%2,%3};\n"
        : "+f"(d[0]), "+f"(d[1]), "+f"(d[2]), "+f"(d[3])
        : "r"(a[0]), "r"(a[1]), "r"(a[2]), "r"(a[3]), "r"(b[0]), "r"(b[1]));
}
__device__ __forceinline__ uint32_t pk2h(float a, float b) {
    __half2 t = __floats2half2_rn(a, b);
    return *reinterpret_cast<uint32_t*>(&t);
}

extern __shared__ char dynsm[];

// ---------------------------------------------------------------------------
// Generic GEMM arguments. batched==0: blockIdx.z selects the operand set
// (merged projections). batched==1: blockIdx.z is the batch index.
// mode: 0 = fp32 out (+bias, *scale)
//       1 = f16 hi/lo split out (+bias, *scale)
//       2 = exp epilogue: e = exp(acc*ascale); split out + row-sum partials
//       3 = fp32 out scaled by rsum[row] (AV normalization)
// ---------------------------------------------------------------------------
struct GArgs {
    const __half* Ah[3]; const __half* Al[3];
    const __half* Bh[3]; const __half* Bl[3];
    float* Cf[3]; __half* Ch[3]; __half* Cl[3];
    const float* bias[3];
    int mode[3];
    long long lda, ldb, ldc;
    long long sA, sB, sC;
    int K, batched;
    float ascale;
    float* part;
    const float* rsum;
};

__global__ __launch_bounds__(256, 2) void gemm_f16(GArgs p)
{
    const uint32_t sbase = (uint32_t)__cvta_generic_to_shared(dynsm);
    const int tid = threadIdx.x, lane = tid & 31, warp = tid >> 5;
    const int wm = warp & 1, wn = warp >> 1;      // 2 x 4 warps
    const int q = lane & 3, g = lane >> 2;

    const int zi = p.batched ? 0 : (int)blockIdx.z;
    const long long bz = p.batched ? (long long)blockIdx.z : 0;
    const int mode = p.mode[zi];

    const long long m0 = (long long)blockIdx.y * BM;
    const long long n0 = (long long)blockIdx.x * BN;

    const char* Ahb = (const char*)(p.Ah[zi] + bz * p.sA + m0 * p.lda);
    const char* Alb = (const char*)(p.Al[zi] + bz * p.sA + m0 * p.lda);
    const char* Bhb = (const char*)(p.Bh[zi] + bz * p.sB + n0 * p.ldb);
    const char* Blb = (const char*)(p.Bl[zi] + bz * p.sB + n0 * p.ldb);

    const uint32_t aoff = (uint32_t)((wm * 64 + (lane & 15)) * 80 + ((lane >> 4) << 4));
    const uint32_t boff = (uint32_t)((wn * 32 + ((lane >> 4) & 1) * 8 + (lane & 7)) * 80
                                     + ((lane >> 3) & 1) * 16);

    float acc[4][4][4];
    #pragma unroll
    for (int i = 0; i < 4; ++i)
        #pragma unroll
        for (int j = 0; j < 4; ++j)
            #pragma unroll
            for (int r = 0; r < 4; ++r) acc[i][j][r] = 0.0f;

    const int KT = p.K / BK;
    const long long lda2 = p.lda * 2, ldb2 = p.ldb * 2;

    auto load_tile = [&](int kt) {
        const uint32_t sb = sbase + (kt & 1) * STAGE_B;
        const long long kb = (long long)kt * (BK * 2);
        const int row = tid >> 2, c = (tid & 3) * 16;
        #pragma unroll
        for (int pp = 0; pp < 2; ++pp) {
            const int r = row + pp * 64;
            const uint32_t d = (uint32_t)(r * 80 + c);
            const long long ga = (long long)r * lda2 + kb + c;
            const long long gb = (long long)r * ldb2 + kb + c;
            cp16(sb + AH_O + d, Ahb + ga);
            cp16(sb + AL_O + d, Alb + ga);
            cp16(sb + BH_O + d, Bhb + gb);
            cp16(sb + BL_O + d, Blb + gb);
        }
        cp_commit();
    };

    auto compute = [&](int kt) {
        const uint32_t sb = sbase + (kt & 1) * STAGE_B;
        #pragma unroll
        for (int kk = 0; kk < 2; ++kk) {
            const uint32_t ka = kk * 32;
            uint32_t ah[4][4], al[4][4];
            #pragma unroll
            for (int i = 0; i < 4; ++i) {
                ldsm4(ah[i], sb + AH_O + aoff + i * 1280 + ka);
                ldsm4(al[i], sb + AL_O + aoff + i * 1280 + ka);
            }
            uint32_t bh[4][2], bl[4][2];
            #pragma unroll
            for (int jp = 0; jp < 2; ++jp) {
                uint32_t rb[4];
                ldsm4(rb, sb + BH_O + boff + jp * 1280 + ka);
                bh[2*jp][0] = rb[0]; bh[2*jp][1] = rb[1];
                bh[2*jp+1][0] = rb[2]; bh[2*jp+1][1] = rb[3];
                ldsm4(rb, sb + BL_O + boff + jp * 1280 + ka);
                bl[2*jp][0] = rb[0]; bl[2*jp][1] = rb[1];
                bl[2*jp+1][0] = rb[2]; bl[2*jp+1][1] = rb[3];
            }
            #pragma unroll
            for (int i = 0; i < 4; ++i)
                #pragma unroll
                for (int j = 0; j < 4; ++j) {
                    mma16(acc[i][j], ah[i], bh[j]);
                    mma16(acc[i][j], al[i], bh[j]);
                    mma16(acc[i][j], ah[i], bl[j]);
                }
        }
    };

    // Single-barrier double-buffered mainloop.
    load_tile(0);
    for (int kt = 0; kt < KT; ++kt) {
        cp_wait<0>();
        __syncthreads();
        if (kt + 1 < KT) load_tile(kt + 1);
        compute(kt);
    }

    // ---------------- epilogues ----------------
    if (mode == 2) {
        // exp + split + deterministic row-sum partials
        __syncthreads();                           // tiles dead; reuse smem
        float (*srows)[4] = reinterpret_cast<float(*)[4]>(dynsm);
        __half* Ch = p.Ch[zi]; __half* Cl = p.Cl[zi];
        #pragma unroll
        for (int i = 0; i < 4; ++i) {
            float p0 = 0.0f, p1 = 0.0f;
            const long long r0 = m0 + wm * 64 + i * 16 + g;
            #pragma unroll
            for (int j = 0; j < 4; ++j) {
                float e0 = __expf(acc[i][j][0] * p.ascale);
                float e1 = __expf(acc[i][j][1] * p.ascale);
                float e2 = __expf(acc[i][j][2] * p.ascale);
                float e3 = __expf(acc[i][j][3] * p.ascale);
                p0 += e0 + e1;  p1 += e2 + e3;
                const long long c0 = n0 + wn * 32 + j * 8 + 2 * q;
                __half h0 = __float2half_rn(e0), h1 = __float2half_rn(e1);
                __half h2 = __float2half_rn(e2), h3 = __float2half_rn(e3);
                float l0 = e0 - __half2float(h0), l1 = e1 - __half2float(h1);
                float l2 = e2 - __half2float(h2), l3 = e3 - __half2float(h3);
                *(uint32_t*)(Ch + bz * p.sC + r0 * p.ldc + c0)       = pk2h(e0, e1);
                *(uint32_t*)(Ch + bz * p.sC + (r0 + 8) * p.ldc + c0) = pk2h(e2, e3);
                *(uint32_t*)(Cl + bz * p.sC + r0 * p.ldc + c0)       = pk2h(l0, l1);
                *(uint32_t*)(Cl + bz * p.sC + (r0 + 8) * p.ldc + c0) = pk2h(l2, l3);
            }
            // reduce over q (cols within this warp's 32-col strip)
            p0 += __shfl_xor_sync(0xFFFFFFFFu, p0, 1);
            p0 += __shfl_xor_sync(0xFFFFFFFFu, p0, 2);
            p1 += __shfl_xor_sync(0xFFFFFFFFu, p1, 1);
            p1 += __shfl_xor_sync(0xFFFFFFFFu, p1, 2);
            if (q == 0) {
                srows[wm * 64 + i * 16 + g][wn]     = p0;
                srows[wm * 64 + i * 16 + g + 8][wn] = p1;
            }
        }
        __syncthreads();
        if (tid < 128) {
            float s = srows[tid][0] + srows[tid][1] + srows[tid][2] + srows[tid][3];
            p.part[((bz << 10) + m0 + tid) * 8 + blockIdx.x] = s;
        }
        return;
    }

    if (mode == 3) {
        float* Cf = p.Cf[zi];
        #pragma unroll
        for (int i = 0; i < 4; ++i) {
            const long long r0 = m0 + wm * 64 + i * 16 + g;
            const float rs0 = p.rsum[(bz << 10) + r0];
            const float rs1 = p.rsum[(bz << 10) + r0 + 8];
            #pragma unroll
            for (int j = 0; j < 4; ++j) {
                const long long c0 = n0 + wn * 32 + j * 8 + 2 * q;
                *(float2*)(Cf + bz * p.sC + r0 * p.ldc + c0) =
                    make_float2(acc[i][j][0] * rs0, acc[i][j][1] * rs0);
                *(float2*)(Cf + bz * p.sC + (r0 + 8) * p.ldc + c0) =
                    make_float2(acc[i][j][2] * rs1, acc[i][j][3] * rs1);
            }
        }
        return;
    }

    // modes 0 / 1: f = acc*ascale + bias
    const float* bias = p.bias[zi];
    #pragma unroll
    for (int i = 0; i < 4; ++i) {
        const long long r0 = m0 + wm * 64 + i * 16 + g;
        #pragma unroll
        for (int j = 0; j < 4; ++j) {
            const long long c0 = n0 + wn * 32 + j * 8 + 2 * q;
            const float b0 = bias ? bias[c0]     : 0.0f;
            const float b1 = bias ? bias[c0 + 1] : 0.0f;
            float x0 = acc[i][j][0] * p.ascale + b0;
            float x1 = acc[i][j][1] * p.ascale + b1;
            float x2 = acc[i][j][2] * p.ascale + b0;
            float x3 = acc[i][j][3] * p.ascale + b1;
            if (mode == 0) {
                float* Cf = p.Cf[zi];
                *(float2*)(Cf + bz * p.sC + r0 * p.ldc + c0)       = make_float2(x0, x1);
                *(float2*)(Cf + bz * p.sC + (r0 + 8) * p.ldc + c0) = make_float2(x2, x3);
            } else {
                __half* Ch = p.Ch[zi]; __half* Cl = p.Cl[zi];
                __half h0 = __float2half_rn(x0), h1 = __float2half_rn(x1);
                __half h2 = __float2half_rn(x2), h3 = __float2half_rn(x3);
                float l0 = x0 - __half2float(h0), l1 = x1 - __half2float(h1);
                float l2 = x2 - __half2float(h2), l3 = x3 - __half2float(h3);
                *(uint32_t*)(Ch + bz * p.sC + r0 * p.ldc + c0)       = pk2h(x0, x1);
                *(uint32_t*)(Ch + bz * p.sC + (r0 + 8) * p.ldc + c0) = pk2h(x2, x3);
                *(uint32_t*)(Cl + bz * p.sC + r0 * p.ldc + c0)       = pk2h(l0, l1);
                *(uint32_t*)(Cl + bz * p.sC + (r0 + 8) * p.ldc + c0) = pk2h(l2, l3);
            }
        }
    }
}

// ---------------------------------------------------------------------------
// fp32 -> (hi, lo) f16 split of x*scale; 3 arrays fused via blockIdx.y.
// ---------------------------------------------------------------------------
struct SplitArgs {
    const float* x[3];
    __half* h[3];
    __half* l[3];
};

__global__ __launch_bounds__(256) void split3_kernel(SplitArgs args, float scale)
{
    const int a = blockIdx.y;
    const long long i = (long long)blockIdx.x * 256 + threadIdx.x;
    float4 v = ((const float4*)args.x[a])[i];
    v.x *= scale; v.y *= scale; v.z *= scale; v.w *= scale;
    __half h0 = __float2half_rn(v.x), h1 = __float2half_rn(v.y);
    __half h2 = __float2half_rn(v.z), h3 = __float2half_rn(v.w);
    float l0 = v.x - __half2float(h0), l1 = v.y - __half2float(h1);
    float l2 = v.z - __half2float(h2), l3 = v.w - __half2float(h3);
    ((uint2*)args.h[a])[i] = make_uint2(pk2h(v.x, v.y), pk2h(v.z, v.w));
    ((uint2*)args.l[a])[i] = make_uint2(pk2h(l0, l1), pk2h(l2, l3));
}

// ---------------------------------------------------------------------------
// Transpose + split V:  v[(s*16+nb)*1024 + f] (fp32) -> vt{h,l}[nb][f][s]
// ---------------------------------------------------------------------------
__global__ __launch_bounds__(256) void transpose_split_kernel(
    const float* __restrict__ v, __half* __restrict__ vth,
    __half* __restrict__ vtl)
{
    __shared__ float t[64][65];
    const int nb = blockIdx.z;
    const int s0 = blockIdx.x * 64, f0 = blockIdx.y * 64;
    const int c = threadIdx.x & 63, r0 = threadIdx.x >> 6;

    #pragma unroll
    for (int rr = r0; rr < 64; rr += 4)
        t[rr][c] = v[(long long)((s0 + rr) * 16 + nb) * 1024 + f0 + c];
    __syncthreads();

    __half* oh = vth + (size_t)nb * 1024 * 1024;
    __half* ol = vtl + (size_t)nb * 1024 * 1024;
    #pragma unroll
    for (int rr = r0; rr < 64; rr += 4) {
        float x = t[c][rr];
        __half h = __float2half_rn(x);
        float lo = x - __half2float(h);
        size_t idx = (size_t)(f0 + rr) * 1024 + s0 + c;
        oh[idx] = h;
        ol[idx] = __float2half_rn(lo);
    }
}

// ---------------------------------------------------------------------------
// rsum[row] = 1 / sum_{cb<8} part[row*8+cb]
// ---------------------------------------------------------------------------
__global__ __launch_bounds__(256) void rowsum_kernel(
    const float* __restrict__ part, float* __restrict__ rsum)
{
    const int row = blockIdx.x * 256 + threadIdx.x;
    const float4 a = ((const float4*)part)[row * 2];
    const float4 b = ((const float4*)part)[row * 2 + 1];
    rsum[row] = 1.0f / (((a.x + a.y) + (a.z + a.w)) + ((b.x + b.y) + (b.z + b.w)));
}

// ---------------------------------------------------------------------------
// Launch
// ---------------------------------------------------------------------------
extern "C" void kernel_launch(void* const* d_in, const int* in_sizes, int n_in,
                              void* d_out, int out_size)
{
    const float* query = (const float*)d_in[0];
    const float* key   = (const float*)d_in[1];
    const float* value = (const float*)d_in[2];
    const float* wq    = (const float*)d_in[3];
    const float* wk    = (const float*)d_in[4];
    const float* wv    = (const float*)d_in[5];
    const float* bias  = (const float*)d_in[6];
    float* out = (float*)d_out;

    __half *xqh,*xql,*xkh,*xkl,*xvh,*xvl;
    __half *wqh,*wql,*wkh,*wkl,*wvh,*wvl;
    __half *qh,*ql,*kh,*kl,*vth,*vtl,*ath,*atl;
    float *vf, *part, *rsum;
    cudaGetSymbolAddress((void**)&xqh, g_xq_h); cudaGetSymbolAddress((void**)&xql, g_xq_l);
    cudaGetSymbolAddress((void**)&xkh, g_xk_h); cudaGetSymbolAddress((void**)&xkl, g_xk_l);
    cudaGetSymbolAddress((void**)&xvh, g_xv_h); cudaGetSymbolAddress((void**)&xvl, g_xv_l);
    cudaGetSymbolAddress((void**)&wqh, g_wq_h); cudaGetSymbolAddress((void**)&wql, g_wq_l);
    cudaGetSymbolAddress((void**)&wkh, g_wk_h); cudaGetSymbolAddress((void**)&wkl, g_wk_l);
    cudaGetSymbolAddress((void**)&wvh, g_wv_h); cudaGetSymbolAddress((void**)&wvl, g_wv_l);
    cudaGetSymbolAddress((void**)&qh,  g_q_h);  cudaGetSymbolAddress((void**)&ql,  g_q_l);
    cudaGetSymbolAddress((void**)&kh,  g_k_h);  cudaGetSymbolAddress((void**)&kl,  g_k_l);
    cudaGetSymbolAddress((void**)&vth, g_vt_h); cudaGetSymbolAddress((void**)&vtl, g_vt_l);
    cudaGetSymbolAddress((void**)&ath, g_a_h);  cudaGetSymbolAddress((void**)&atl, g_a_l);
    cudaGetSymbolAddress((void**)&vf,  g_v);
    cudaGetSymbolAddress((void**)&part, g_part);
    cudaGetSymbolAddress((void**)&rsum, g_rsum);

    cudaFuncSetAttribute(gemm_f16, cudaFuncAttributeMaxDynamicSharedMemorySize, SMEM_REQ);

    const long long MM = 1024LL * 1024;

    // 1) splits: inputs (scale 1), weights (scale 32)
    {
        SplitArgs in;
        in.x[0] = query; in.h[0] = xqh; in.l[0] = xql;
        in.x[1] = key;   in.h[1] = xkh; in.l[1] = xkl;
        in.x[2] = value; in.h[2] = xvh; in.l[2] = xvl;
        split3_kernel<<<dim3(16384, 3), 256>>>(in, 1.0f);
        SplitArgs w;
        w.x[0] = wq; w.h[0] = wqh; w.l[0] = wql;
        w.x[1] = wk; w.h[1] = wkh; w.l[1] = wkl;
        w.x[2] = wv; w.h[2] = wvh; w.l[2] = wvl;
        split3_kernel<<<dim3(1024, 3), 256>>>(w, 32.0f);
    }

    // 2) merged projections: z in {q, k, v}. f = acc/32 + bias.
    {
        GArgs a = {};
        a.Ah[0] = xqh; a.Al[0] = xql; a.Bh[0] = wqh; a.Bl[0] = wql;
        a.Ah[1] = xkh; a.Al[1] = xkl; a.Bh[1] = wkh; a.Bl[1] = wkl;
        a.Ah[2] = xvh; a.Al[2] = xvl; a.Bh[2] = wvh; a.Bl[2] = wvl;
        a.Ch[0] = qh; a.Cl[0] = ql;
        a.Ch[1] = kh; a.Cl[1] = kl;
        a.Cf[2] = vf;
        a.bias[0] = bias; a.bias[1] = bias + 1024; a.bias[2] = bias + 2048;
        a.mode[0] = 1; a.mode[1] = 1; a.mode[2] = 0;
        a.lda = 1024; a.ldb = 1024; a.ldc = 1024;
        a.sA = 0; a.sB = 0; a.sC = 0;
        a.K = 1024; a.batched = 0; a.ascale = 1.0f / 32.0f;
        gemm_f16<<<dim3(8, 128, 3), 256, SMEM_REQ>>>(a);
    }

    // 3) V transpose + split -> vt[nb][f][s]
    transpose_split_kernel<<<dim3(16, 16, 16), 256>>>(vf, vth, vtl);

    // 4) scores + fused exp/partial-rowsum: e = exp(q.k^T / 32), split out.
    {
        GArgs a = {};
        a.Ah[0] = qh; a.Al[0] = ql; a.Bh[0] = kh; a.Bl[0] = kl;
        a.Ch[0] = ath; a.Cl[0] = atl;
        a.mode[0] = 2;
        a.lda = 16384; a.ldb = 16384; a.ldc = 1024;
        a.sA = 1024; a.sB = 1024; a.sC = MM;
        a.K = 1024; a.batched = 1; a.ascale = 1.0f / 32.0f;
        a.part = part;
        gemm_f16<<<dim3(8, 8, 16), 256, SMEM_REQ>>>(a);
    }

    // 5) row-sum reciprocal
    rowsum_kernel<<<64, 256>>>(part, rsum);

    // 6) out = (e @ vt^T) * rsum[row]
    {
        GArgs a = {};
        a.Ah[0] = ath; a.Al[0] = atl; a.Bh[0] = vth; a.Bl[0] = vtl;
        a.Cf[0] = out;
        a.mode[0] = 3;
        a.lda = 1024; a.ldb = 1024; a.ldc = 16384;
        a.sA = MM; a.sB = MM; a.sC = 1024;
        a.K = 1024; a.batched = 1; a.ascale = 1.0f;
        a.rsum = rsum;
        gemm_f16<<<dim3(8, 8, 16), 256, SMEM_REQ>>>(a);
    }
}